// round 4
// baseline (speedup 1.0000x reference)
#include <cuda_runtime.h>
#include <cuda_bf16.h>
#include <cstdint>

// ===========================================================================
// MyRGCNConv via legacy tensor path (sm_100 base: mma.sync + ldmatrix + cp.async)
//  Phase 0: W[2048,256] f32 -> Bt_hi/Bt_lo bf16, transposed to [256 n][2048 k]
//  Phase 1: agg[c, r*256+d] per (center, relation); emitted as bf16 hi/lo
//  Phase 2: out = (Ah*Bh + Al*Bh + Ah*Bl) / deg,  CTA tile 128x256, BK=32
// ===========================================================================

#define DFEAT 256
#define NRELS 8
#define KDIM  2048
#define MAXM  50176

__device__ __align__(16) __nv_bfloat16 g_ahi[(size_t)MAXM * KDIM];
__device__ __align__(16) __nv_bfloat16 g_alo[(size_t)MAXM * KDIM];
__device__ __align__(16) __nv_bfloat16 g_bhi[(size_t)DFEAT * KDIM];  // [n][k]
__device__ __align__(16) __nv_bfloat16 g_blo[(size_t)DFEAT * KDIM];

// ---------------------------------------------------------------------------
__device__ __forceinline__ uint32_t smem_u32(const void* p) {
    uint32_t a;
    asm("{ .reg .u64 t; cvta.to.shared.u64 t, %1; cvt.u32.u64 %0, t; }"
        : "=r"(a) : "l"(p));
    return a;
}
__device__ __forceinline__ void cp16(uint32_t dst, const void* src) {
    asm volatile("cp.async.cg.shared.global [%0], [%1], 16;"
                 :: "r"(dst), "l"(src));
}
__device__ __forceinline__ void ldm_x4(uint32_t& r0, uint32_t& r1,
                                       uint32_t& r2, uint32_t& r3, uint32_t a) {
    asm volatile("ldmatrix.sync.aligned.m8n8.x4.shared.b16 {%0,%1,%2,%3}, [%4];"
                 : "=r"(r0), "=r"(r1), "=r"(r2), "=r"(r3) : "r"(a));
}
__device__ __forceinline__ void mma_bf16(float* c, const uint32_t* a,
                                         uint32_t b0, uint32_t b1) {
    asm volatile(
        "mma.sync.aligned.m16n8k16.row.col.f32.bf16.bf16.f32 "
        "{%0,%1,%2,%3}, {%4,%5,%6,%7}, {%8,%9}, {%0,%1,%2,%3};"
        : "+f"(c[0]), "+f"(c[1]), "+f"(c[2]), "+f"(c[3])
        : "r"(a[0]), "r"(a[1]), "r"(a[2]), "r"(a[3]), "r"(b0), "r"(b1));
}

// ---------------------------------------------------------------------------
// Phase 0: weight transpose + bf16 split
// ---------------------------------------------------------------------------
__global__ void __launch_bounds__(256) wsplit_kernel(const float* __restrict__ w) {
    int i = blockIdx.x * 256 + threadIdx.x;   // over 256*2048
    int n = i >> 11;
    int k = i & 2047;
    float f = w[(size_t)k * DFEAT + n];
    __nv_bfloat16 h = __float2bfloat16(f);
    __nv_bfloat16 l = __float2bfloat16(f - __bfloat162float(h));
    g_bhi[i] = h;
    g_blo[i] = l;
}

// ---------------------------------------------------------------------------
// Phase 1: per-center aggregation -> bf16 hi/lo. 1 block = 1 center,
// 128 threads = 2 features each; no smem/syncs, predicated register accum.
// ---------------------------------------------------------------------------
__global__ void __launch_bounds__(128) agg_kernel(
    const float* __restrict__ x,
    const int*   __restrict__ ptr,
    const int*   __restrict__ idx,
    const int*   __restrict__ rel,
    int C)
{
    const int c = blockIdx.x;
    const int t = threadIdx.x;

    float a0[NRELS], a1[NRELS];
#pragma unroll
    for (int r = 0; r < NRELS; ++r) { a0[r] = 0.f; a1[r] = 0.f; }

    if (c < C) {
        const int beg = ptr[c];
        const int end = ptr[c + 1];
#pragma unroll 8
        for (int e = beg; e < end; ++e) {
            const int node = __ldg(idx + e);
            const int re   = __ldg(rel + e);
            const float2 v = __ldg((const float2*)(x + (size_t)node * DFEAT) + t);
#pragma unroll
            for (int r = 0; r < NRELS; ++r) {
                const bool m = (re == r);
                a0[r] += m ? v.x : 0.f;
                a1[r] += m ? v.y : 0.f;
            }
        }
    }

    const size_t base = (size_t)c * KDIM;
#pragma unroll
    for (int r = 0; r < NRELS; ++r) {
        const float f0 = a0[r], f1 = a1[r];
        __nv_bfloat16 h0 = __float2bfloat16(f0);
        __nv_bfloat16 h1 = __float2bfloat16(f1);
        __nv_bfloat16 l0 = __float2bfloat16(f0 - __bfloat162float(h0));
        __nv_bfloat16 l1 = __float2bfloat16(f1 - __bfloat162float(h1));
        __nv_bfloat162 hh; hh.x = h0; hh.y = h1;
        __nv_bfloat162 ll; ll.x = l0; ll.y = l1;
        ((__nv_bfloat162*)(g_ahi + base + r * DFEAT))[t] = hh;
        ((__nv_bfloat162*)(g_alo + base + r * DFEAT))[t] = ll;
    }
}

// ---------------------------------------------------------------------------
// Phase 2: GEMM  out[M,256] = A[M,2048] * Bt[256,2048]^T, / deg.
// CTA tile 128x256, BK=32, 512 threads (16 warps of 32x64), double-buffered
// cp.async. Smem rows padded to 80B -> ldmatrix conflict-free.
// A streamed from DRAM exactly once (grid.y removed).
// ---------------------------------------------------------------------------
#define BK     32
#define ROWB   80u                     // bytes per smem row (32 bf16 + 8 pad)
#define OFF_AH 0u
#define OFF_AL 10240u
#define OFF_BH 20480u
#define OFF_BL 40960u
#define STAGE  61440u
#define SMEMSZ (2u * STAGE)            // 122880 bytes

__global__ void __launch_bounds__(512, 1) gemm_kernel(
    const int* __restrict__ ptr,
    float*     __restrict__ out,
    int C)
{
    extern __shared__ char smem[];
    const uint32_t sbase = smem_u32(smem);
    const int tid  = threadIdx.x;
    const int lane = tid & 31;
    const int wid  = tid >> 5;
    const int bm   = blockIdx.x * 128;

    const int warp_m = (wid & 3) * 32;      // 4 m-groups
    const int warp_n = (wid >> 2) * 64;     // 4 n-groups

    const __nv_bfloat16* __restrict__ Ah = g_ahi + (size_t)bm * KDIM;
    const __nv_bfloat16* __restrict__ Al = g_alo + (size_t)bm * KDIM;

    float acc[2][8][4];
#pragma unroll
    for (int i = 0; i < 2; ++i)
#pragma unroll
        for (int j = 0; j < 8; ++j)
#pragma unroll
            for (int q = 0; q < 4; ++q) acc[i][j][q] = 0.f;

    // loader: A hi+lo = 1024 16B chunks (2/thread), B hi+lo = 2048 (4/thread)
#define LOAD_STAGE(kt, buf)                                                     \
    do {                                                                        \
        const int      k0_ = (kt) * BK;                                         \
        const uint32_t sb_ = sbase + (uint32_t)(buf) * STAGE;                   \
        _Pragma("unroll")                                                       \
        for (int j_ = 0; j_ < 2; ++j_) {                                        \
            const int c_   = tid + j_ * 512;       /* 0..1023 */                \
            const int mat_ = c_ >> 9;                                           \
            const int row_ = (c_ >> 2) & 127;                                   \
            const int col_ = c_ & 3;                                            \
            const __nv_bfloat16* s_ = (mat_ ? Al : Ah) +                        \
                (size_t)row_ * KDIM + k0_ + col_ * 8;                           \
            cp16(sb_ + (mat_ ? OFF_AL : OFF_AH) +                               \
                 (uint32_t)row_ * ROWB + col_ * 16, s_);                        \
        }                                                                       \
        _Pragma("unroll")                                                       \
        for (int j_ = 0; j_ < 4; ++j_) {                                        \
            const int c_   = tid + j_ * 512;       /* 0..2047 */                \
            const int mat_ = c_ >> 10;                                          \
            const int row_ = (c_ >> 2) & 255;                                   \
            const int col_ = c_ & 3;                                            \
            const __nv_bfloat16* s_ = (mat_ ? g_blo : g_bhi) +                  \
                (size_t)row_ * KDIM + k0_ + col_ * 8;                           \
            cp16(sb_ + (mat_ ? OFF_BL : OFF_BH) +                               \
                 (uint32_t)row_ * ROWB + col_ * 16, s_);                        \
        }                                                                       \
        asm volatile("cp.async.commit_group;");                                 \
    } while (0)

    // ldmatrix lane address components
    const uint32_t a_roff = (uint32_t)(warp_m + (lane & 15)) * ROWB +
                            (((uint32_t)lane >> 4) & 1) * 16;
    const uint32_t b_roff = (uint32_t)(warp_n + (((lane >> 4) & 1) * 8) + (lane & 7)) * ROWB +
                            (((uint32_t)lane >> 3) & 1) * 16;

    const int KT = KDIM / BK;      // 64
    LOAD_STAGE(0, 0);

    for (int kt = 0; kt < KT; ++kt) {
        const int buf = kt & 1;
        if (kt + 1 < KT) {
            LOAD_STAGE(kt + 1, buf ^ 1);
            asm volatile("cp.async.wait_group 1;");
        } else {
            asm volatile("cp.async.wait_group 0;");
        }
        __syncthreads();

        const uint32_t sb = sbase + (uint32_t)buf * STAGE;
#pragma unroll
        for (int kf = 0; kf < 2; ++kf) {
            const uint32_t kfo = (uint32_t)kf * 32;

            uint32_t ah[2][4], al[2][4], b[4][4];
#pragma unroll
            for (int mf = 0; mf < 2; ++mf)
                ldm_x4(ah[mf][0], ah[mf][1], ah[mf][2], ah[mf][3],
                       sb + OFF_AH + a_roff + (uint32_t)mf * 16 * ROWB + kfo);
#pragma unroll
            for (int np = 0; np < 4; ++np)
                ldm_x4(b[np][0], b[np][1], b[np][2], b[np][3],
                       sb + OFF_BH + b_roff + (uint32_t)np * 16 * ROWB + kfo);

            // term 1: Ah * Bh
#pragma unroll
            for (int mf = 0; mf < 2; ++mf)
#pragma unroll
                for (int nf = 0; nf < 8; ++nf) {
                    const int s = (nf & 1) * 2;
                    mma_bf16(acc[mf][nf], ah[mf], b[nf >> 1][s], b[nf >> 1][s + 1]);
                }

            // term 2: Al * Bh
#pragma unroll
            for (int mf = 0; mf < 2; ++mf)
                ldm_x4(al[mf][0], al[mf][1], al[mf][2], al[mf][3],
                       sb + OFF_AL + a_roff + (uint32_t)mf * 16 * ROWB + kfo);
#pragma unroll
            for (int mf = 0; mf < 2; ++mf)
#pragma unroll
                for (int nf = 0; nf < 8; ++nf) {
                    const int s = (nf & 1) * 2;
                    mma_bf16(acc[mf][nf], al[mf], b[nf >> 1][s], b[nf >> 1][s + 1]);
                }

            // term 3: Ah * Bl  (overwrite b[] with lo fragments)
#pragma unroll
            for (int np = 0; np < 4; ++np)
                ldm_x4(b[np][0], b[np][1], b[np][2], b[np][3],
                       sb + OFF_BL + b_roff + (uint32_t)np * 16 * ROWB + kfo);
#pragma unroll
            for (int mf = 0; mf < 2; ++mf)
#pragma unroll
                for (int nf = 0; nf < 8; ++nf) {
                    const int s = (nf & 1) * 2;
                    mma_bf16(acc[mf][nf], ah[mf], b[nf >> 1][s], b[nf >> 1][s + 1]);
                }
        }
        __syncthreads();
    }

    // epilogue: /deg, store
#pragma unroll
    for (int mf = 0; mf < 2; ++mf) {
        const int r0 = bm + warp_m + mf * 16 + (lane >> 2);
        const int r1 = r0 + 8;
        float inv0 = 0.f, inv1 = 0.f;
        if (r0 < C) inv0 = 1.f / (float)(__ldg(ptr + r0 + 1) - __ldg(ptr + r0));
        if (r1 < C) inv1 = 1.f / (float)(__ldg(ptr + r1 + 1) - __ldg(ptr + r1));
#pragma unroll
        for (int nf = 0; nf < 8; ++nf) {
            const int col = warp_n + nf * 8 + (lane & 3) * 2;
            if (r0 < C) {
                float2 o; o.x = acc[mf][nf][0] * inv0; o.y = acc[mf][nf][1] * inv0;
                *(float2*)(out + (size_t)r0 * DFEAT + col) = o;
            }
            if (r1 < C) {
                float2 o; o.x = acc[mf][nf][2] * inv1; o.y = acc[mf][nf][3] * inv1;
                *(float2*)(out + (size_t)r1 * DFEAT + col) = o;
            }
        }
    }
}

// ---------------------------------------------------------------------------
extern "C" void kernel_launch(void* const* d_in, const int* in_sizes, int n_in,
                              void* d_out, int out_size) {
    const float* x   = (const float*)d_in[0];
    const float* w   = (const float*)d_in[1];
    const int*   ptr = (const int*)d_in[2];
    const int*   idx = (const int*)d_in[3];
    const int*   rel = (const int*)d_in[4];
    float*       out = (float*)d_out;

    const int C    = in_sizes[2] - 1;
    const int nblk = (C + 127) / 128;

    cudaFuncSetAttribute(gemm_kernel,
                         cudaFuncAttributeMaxDynamicSharedMemorySize, SMEMSZ);

    wsplit_kernel<<<(DFEAT * KDIM) / 256, 256>>>(w);
    agg_kernel<<<nblk * 128, 128>>>(x, ptr, idx, rel, C);
    gemm_kernel<<<nblk, 512, SMEMSZ>>>(ptr, out, C);
}

// round 5
// speedup vs baseline: 1.0500x; 1.0500x over previous
#include <cuda_runtime.h>
#include <cuda_bf16.h>
#include <cstdint>

// ===========================================================================
// MyRGCNConv, fused:
//  Phase 0a: W[2048,256] f32 -> Bt_hi/Bt_lo bf16, transposed to [256 n][2048 k]
//  Phase 0b: per-center counting sort of edges by relation (g_snode, g_roff)
//  Phase 1:  single fused kernel: per CTA (128 centers x 256 out):
//            for each K-chunk (rel r, 32 feats): gather-sum x rows -> bf16
//            hi/lo A tile in smem, 3-term bf16 MMA (Ah*Bh + Al*Bh + Ah*Bl),
//            epilogue /deg.
// ===========================================================================

#define DFEAT 256
#define NRELS 8
#define KDIM  2048
#define EMAX  1048576
#define CMAX  50048

__device__ __align__(16) __nv_bfloat16 g_bhi[(size_t)DFEAT * KDIM];  // [n][k]
__device__ __align__(16) __nv_bfloat16 g_blo[(size_t)DFEAT * KDIM];
__device__ int   g_snode[EMAX];          // edge target nodes, rel-sorted per center
__device__ uint2 g_roff[CMAX];           // packed 8 x u8 relation start offsets

// ---------------------------------------------------------------------------
__device__ __forceinline__ uint32_t smem_u32(const void* p) {
    uint32_t a;
    asm("{ .reg .u64 t; cvta.to.shared.u64 t, %1; cvt.u32.u64 %0, t; }"
        : "=r"(a) : "l"(p));
    return a;
}
__device__ __forceinline__ void cp16(uint32_t dst, const void* src) {
    asm volatile("cp.async.cg.shared.global [%0], [%1], 16;"
                 :: "r"(dst), "l"(src));
}
__device__ __forceinline__ void ldm_x4(uint32_t& r0, uint32_t& r1,
                                       uint32_t& r2, uint32_t& r3, uint32_t a) {
    asm volatile("ldmatrix.sync.aligned.m8n8.x4.shared.b16 {%0,%1,%2,%3}, [%4];"
                 : "=r"(r0), "=r"(r1), "=r"(r2), "=r"(r3) : "r"(a));
}
__device__ __forceinline__ void mma_bf16(float* c, const uint32_t* a,
                                         uint32_t b0, uint32_t b1) {
    asm volatile(
        "mma.sync.aligned.m16n8k16.row.col.f32.bf16.bf16.f32 "
        "{%0,%1,%2,%3}, {%4,%5,%6,%7}, {%8,%9}, {%0,%1,%2,%3};"
        : "+f"(c[0]), "+f"(c[1]), "+f"(c[2]), "+f"(c[3])
        : "r"(a[0]), "r"(a[1]), "r"(a[2]), "r"(a[3]), "r"(b0), "r"(b1));
}

// ---------------------------------------------------------------------------
// Phase 0a: weight transpose + bf16 split
// ---------------------------------------------------------------------------
__global__ void __launch_bounds__(256) wsplit_kernel(const float* __restrict__ w) {
    int i = blockIdx.x * 256 + threadIdx.x;   // over 256*2048
    int n = i >> 11;
    int k = i & 2047;
    float f = w[(size_t)k * DFEAT + n];
    __nv_bfloat16 h = __float2bfloat16(f);
    __nv_bfloat16 l = __float2bfloat16(f - __bfloat162float(h));
    g_bhi[i] = h;
    g_blo[i] = l;
}

// ---------------------------------------------------------------------------
// Phase 0b: per-center counting sort of edges by relation.
// 1 thread per center.
// ---------------------------------------------------------------------------
__global__ void __launch_bounds__(256) sort_kernel(
    const int* __restrict__ ptr,
    const int* __restrict__ idx,
    const int* __restrict__ rel,
    int C)
{
    const int c = blockIdx.x * 256 + threadIdx.x;
    if (c >= C) return;
    const int beg = ptr[c];
    const int end = ptr[c + 1];

    int cnt[NRELS];
#pragma unroll
    for (int r = 0; r < NRELS; ++r) cnt[r] = 0;
    for (int e = beg; e < end; ++e) {
        const int re = __ldg(rel + e);
#pragma unroll
        for (int r = 0; r < NRELS; ++r) cnt[r] += (re == r);
    }
    int st[NRELS];
    int p = 0;
#pragma unroll
    for (int r = 0; r < NRELS; ++r) { st[r] = p; p += cnt[r]; }

    uint2 pk;
    pk.x = (uint32_t)st[0] | ((uint32_t)st[1] << 8) |
           ((uint32_t)st[2] << 16) | ((uint32_t)st[3] << 24);
    pk.y = (uint32_t)st[4] | ((uint32_t)st[5] << 8) |
           ((uint32_t)st[6] << 16) | ((uint32_t)st[7] << 24);
    g_roff[c] = pk;

    int pos[NRELS];
#pragma unroll
    for (int r = 0; r < NRELS; ++r) pos[r] = st[r];
    for (int e = beg; e < end; ++e) {
        const int re = __ldg(rel + e);
        int off = 0;
#pragma unroll
        for (int r = 0; r < NRELS; ++r) if (re == r) off = pos[r]++;
        g_snode[beg + off] = __ldg(idx + e);
    }
}

// ---------------------------------------------------------------------------
// Phase 1: fused gather + GEMM.
// CTA: 128 centers x 256 outputs, 512 threads (16 warps, tile 32x64 each).
// K loop: 64 chunks of 32 (chunk kt -> relation kt/8, feats (kt%8)*32).
// Producer (all threads): thread t -> center t/4, feature-octet t%4;
//   sum x rows of matching edges, split to bf16 hi/lo, store to smem.
// B chunks double-buffered via cp.async from pre-split g_bhi/g_blo.
// ---------------------------------------------------------------------------
#define ROWB    80u
#define OFF_PTR   0u
#define OFF_ROFF  1024u
#define OFF_NODES 2048u          // 8192 ints = 32KB
#define NODES_CAP 8192
#define OFF_A     34816u         // [stage][hl] 10240 each -> 40960
#define OFF_B     75776u         // [stage][hl] 20480 each -> 81920
#define SMEMSZ    157696u

__global__ void __launch_bounds__(512, 1) fused_kernel(
    const float* __restrict__ x,
    const int*   __restrict__ ptr,
    float*       __restrict__ out,
    int C)
{
    extern __shared__ char smem[];
    const uint32_t sbase = smem_u32(smem);
    int* s_ptr   = (int*)(smem + OFF_PTR);       // 129 entries
    uint2* s_roff = (uint2*)(smem + OFF_ROFF);   // 128 entries
    int* s_nodes = (int*)(smem + OFF_NODES);

    const int tid  = threadIdx.x;
    const int lane = tid & 31;
    const int wid  = tid >> 5;
    const int bm   = blockIdx.x * 128;

    const int warp_m = (wid & 3) * 32;
    const int warp_n = (wid >> 2) * 64;

    // ---- prologue: tile metadata ----
    if (tid < 129) {
        int cc = bm + tid; if (cc > C) cc = C;
        s_ptr[tid] = __ldg(ptr + cc);
    }
    if (tid < 128) {
        const int gc = bm + tid;
        s_roff[tid] = (gc < C) ? __ldg(&g_roff[gc]) : make_uint2(0u, 0u);
    }
    __syncthreads();
    const int ebase = s_ptr[0];
    const int ecnt  = min(s_ptr[128] - ebase, NODES_CAP);
    for (int i = tid; i < ecnt; i += 512) s_nodes[i] = __ldg(&g_snode[ebase + i]);
    __syncthreads();

    // producer mapping
    const int pm = tid >> 2;               // center within tile
    const int pq = tid & 3;                // feature octet
    const int seg = s_ptr[pm] - ebase;
    const int pdeg = s_ptr[pm + 1] - s_ptr[pm];
    const uint2 proff = s_roff[pm];

    float acc[2][8][4];
#pragma unroll
    for (int i = 0; i < 2; ++i)
#pragma unroll
        for (int j = 0; j < 8; ++j)
#pragma unroll
            for (int q = 0; q < 4; ++q) acc[i][j][q] = 0.f;

#define PRODUCE_B(kt, buf)                                                      \
    do {                                                                        \
        const int k0_ = (kt) * 32;                                              \
        const uint32_t sb_ = sbase + OFF_B + (uint32_t)(buf) * 40960u;          \
        _Pragma("unroll")                                                       \
        for (int j_ = 0; j_ < 4; ++j_) {                                        \
            const int c_   = tid + j_ * 512;                                    \
            const int mat_ = c_ >> 10;                                          \
            const int row_ = (c_ >> 2) & 255;                                   \
            const int col_ = c_ & 3;                                            \
            const __nv_bfloat16* s_ = (mat_ ? g_blo : g_bhi) +                  \
                (size_t)row_ * KDIM + k0_ + col_ * 8;                           \
            cp16(sb_ + (uint32_t)mat_ * 20480u +                                \
                 (uint32_t)row_ * ROWB + col_ * 16, s_);                        \
        }                                                                       \
        asm volatile("cp.async.commit_group;");                                 \
    } while (0)

#define PRODUCE_A(kt, buf)                                                      \
    do {                                                                        \
        const int r_  = (kt) >> 3;                                              \
        const int f0_ = ((kt) & 7) * 32 + pq * 8;                               \
        const uint32_t pks_ = (r_ < 4) ? proff.x : proff.y;                     \
        const int js_ = (pks_ >> ((r_ & 3) * 8)) & 0xFF;                        \
        int je_;                                                                \
        if (r_ == 7) je_ = pdeg;                                                \
        else {                                                                  \
            const uint32_t pke_ = (r_ + 1 < 4) ? proff.x : proff.y;             \
            je_ = (pke_ >> (((r_ + 1) & 3) * 8)) & 0xFF;                        \
        }                                                                       \
        float s0=0.f,s1=0.f,s2=0.f,s3=0.f,s4=0.f,s5=0.f,s6=0.f,s7=0.f;          \
        for (int j_ = js_; j_ < je_; ++j_) {                                    \
            const int nd_ = s_nodes[seg + j_];                                  \
            const float4 v0_ = __ldg((const float4*)(x + (size_t)nd_ * DFEAT + f0_)); \
            const float4 v1_ = __ldg((const float4*)(x + (size_t)nd_ * DFEAT + f0_ + 4)); \
            s0 += v0_.x; s1 += v0_.y; s2 += v0_.z; s3 += v0_.w;                 \
            s4 += v1_.x; s5 += v1_.y; s6 += v1_.z; s7 += v1_.w;                 \
        }                                                                       \
        __nv_bfloat162 h01, h23, h45, h67, l01, l23, l45, l67;                  \
        h01.x = __float2bfloat16(s0); h01.y = __float2bfloat16(s1);             \
        h23.x = __float2bfloat16(s2); h23.y = __float2bfloat16(s3);             \
        h45.x = __float2bfloat16(s4); h45.y = __float2bfloat16(s5);             \
        h67.x = __float2bfloat16(s6); h67.y = __float2bfloat16(s7);             \
        l01.x = __float2bfloat16(s0 - __bfloat162float(h01.x));                 \
        l01.y = __float2bfloat16(s1 - __bfloat162float(h01.y));                 \
        l23.x = __float2bfloat16(s2 - __bfloat162float(h23.x));                 \
        l23.y = __float2bfloat16(s3 - __bfloat162float(h23.y));                 \
        l45.x = __float2bfloat16(s4 - __bfloat162float(h45.x));                 \
        l45.y = __float2bfloat16(s5 - __bfloat162float(h45.y));                 \
        l67.x = __float2bfloat16(s6 - __bfloat162float(h67.x));                 \
        l67.y = __float2bfloat16(s7 - __bfloat162float(h67.y));                 \
        uint4 hv_, lv_;                                                         \
        hv_.x = *(uint32_t*)&h01; hv_.y = *(uint32_t*)&h23;                     \
        hv_.z = *(uint32_t*)&h45; hv_.w = *(uint32_t*)&h67;                     \
        lv_.x = *(uint32_t*)&l01; lv_.y = *(uint32_t*)&l23;                     \
        lv_.z = *(uint32_t*)&l45; lv_.w = *(uint32_t*)&l67;                     \
        const uint32_t ad_ = sbase + OFF_A + (uint32_t)(buf) * 20480u +         \
                             (uint32_t)pm * ROWB + pq * 16;                     \
        *(uint4*)(smem + (ad_ - sbase)) = hv_;                                  \
        *(uint4*)(smem + (ad_ - sbase) + 10240u) = lv_;                         \
    } while (0)

    // ldmatrix lane address components
    const uint32_t a_roff = (uint32_t)(warp_m + (lane & 15)) * ROWB +
                            (((uint32_t)lane >> 4) & 1) * 16;
    const uint32_t b_roff = (uint32_t)(warp_n + (((lane >> 4) & 1) * 8) + (lane & 7)) * ROWB +
                            (((uint32_t)lane >> 3) & 1) * 16;

    PRODUCE_B(0, 0);
    PRODUCE_A(0, 0);
    asm volatile("cp.async.wait_group 0;");
    __syncthreads();

    const int KT = KDIM / 32;      // 64
    for (int kt = 0; kt < KT; ++kt) {
        const int buf = kt & 1;
        if (kt + 1 < KT) {
            PRODUCE_B(kt + 1, buf ^ 1);
            PRODUCE_A(kt + 1, buf ^ 1);
        }

        const uint32_t sa = sbase + OFF_A + (uint32_t)buf * 20480u;
        const uint32_t sbb = sbase + OFF_B + (uint32_t)buf * 40960u;
#pragma unroll
        for (int kf = 0; kf < 2; ++kf) {
            const uint32_t kfo = (uint32_t)kf * 32;

            uint32_t ah[2][4], al[2][4], b[4][4];
#pragma unroll
            for (int mf = 0; mf < 2; ++mf)
                ldm_x4(ah[mf][0], ah[mf][1], ah[mf][2], ah[mf][3],
                       sa + a_roff + (uint32_t)mf * 16 * ROWB + kfo);
#pragma unroll
            for (int np = 0; np < 4; ++np)
                ldm_x4(b[np][0], b[np][1], b[np][2], b[np][3],
                       sbb + b_roff + (uint32_t)np * 16 * ROWB + kfo);

            // term 1: Ah * Bh
#pragma unroll
            for (int mf = 0; mf < 2; ++mf)
#pragma unroll
                for (int nf = 0; nf < 8; ++nf) {
                    const int s = (nf & 1) * 2;
                    mma_bf16(acc[mf][nf], ah[mf], b[nf >> 1][s], b[nf >> 1][s + 1]);
                }
            // term 2: Al * Bh
#pragma unroll
            for (int mf = 0; mf < 2; ++mf)
                ldm_x4(al[mf][0], al[mf][1], al[mf][2], al[mf][3],
                       sa + 10240u + a_roff + (uint32_t)mf * 16 * ROWB + kfo);
#pragma unroll
            for (int mf = 0; mf < 2; ++mf)
#pragma unroll
                for (int nf = 0; nf < 8; ++nf) {
                    const int s = (nf & 1) * 2;
                    mma_bf16(acc[mf][nf], al[mf], b[nf >> 1][s], b[nf >> 1][s + 1]);
                }
            // term 3: Ah * Bl (overwrite b with lo fragments)
#pragma unroll
            for (int np = 0; np < 4; ++np)
                ldm_x4(b[np][0], b[np][1], b[np][2], b[np][3],
                       sbb + 20480u + b_roff + (uint32_t)np * 16 * ROWB + kfo);
#pragma unroll
            for (int mf = 0; mf < 2; ++mf)
#pragma unroll
                for (int nf = 0; nf < 8; ++nf) {
                    const int s = (nf & 1) * 2;
                    mma_bf16(acc[mf][nf], ah[mf], b[nf >> 1][s], b[nf >> 1][s + 1]);
                }
        }

        if (kt + 1 < KT) asm volatile("cp.async.wait_group 0;");
        __syncthreads();
    }

    // ---- epilogue: /deg, store ----
#pragma unroll
    for (int mf = 0; mf < 2; ++mf) {
        const int lm0 = warp_m + mf * 16 + (lane >> 2);
        const int lm1 = lm0 + 8;
        const int r0 = bm + lm0;
        const int r1 = bm + lm1;
        float inv0 = 0.f, inv1 = 0.f;
        if (r0 < C) inv0 = 1.f / (float)(s_ptr[lm0 + 1] - s_ptr[lm0]);
        if (r1 < C) inv1 = 1.f / (float)(s_ptr[lm1 + 1] - s_ptr[lm1]);
#pragma unroll
        for (int nf = 0; nf < 8; ++nf) {
            const int col = warp_n + nf * 8 + (lane & 3) * 2;
            if (r0 < C) {
                float2 o; o.x = acc[mf][nf][0] * inv0; o.y = acc[mf][nf][1] * inv0;
                *(float2*)(out + (size_t)r0 * DFEAT + col) = o;
            }
            if (r1 < C) {
                float2 o; o.x = acc[mf][nf][2] * inv1; o.y = acc[mf][nf][3] * inv1;
                *(float2*)(out + (size_t)r1 * DFEAT + col) = o;
            }
        }
    }
}

// ---------------------------------------------------------------------------
extern "C" void kernel_launch(void* const* d_in, const int* in_sizes, int n_in,
                              void* d_out, int out_size) {
    const float* x   = (const float*)d_in[0];
    const float* w   = (const float*)d_in[1];
    const int*   ptr = (const int*)d_in[2];
    const int*   idx = (const int*)d_in[3];
    const int*   rel = (const int*)d_in[4];
    float*       out = (float*)d_out;

    const int C    = in_sizes[2] - 1;
    const int nblk = (C + 127) / 128;

    cudaFuncSetAttribute(fused_kernel,
                         cudaFuncAttributeMaxDynamicSharedMemorySize, SMEMSZ);

    wsplit_kernel<<<(DFEAT * KDIM) / 256, 256>>>(w);
    sort_kernel<<<(C + 255) / 256, 256>>>(ptr, idx, rel, C);
    fused_kernel<<<nblk, 512, SMEMSZ>>>(x, ptr, out, C);
}

// round 7
// speedup vs baseline: 1.4120x; 1.3447x over previous
#include <cuda_runtime.h>
#include <cuda_fp16.h>
#include <cstdint>

// ===========================================================================
// MyRGCNConv, fp16 2-term split:
//  Phase 0a: W[2048,256] f32 -> g_bh fp16, transposed [256 n][2048 k]
//  Phase 0b: per-center counting sort of edges by relation (g_snode, g_roff)
//  Phase 1:  agg over sorted runs -> A = Ah + Al (fp16 hi/lo)
//  Phase 2:  out = (Ah*Bh + Al*Bh) / deg   via m16n8k16 fp16 MMA, f32 accum
// ===========================================================================

#define DFEAT 256
#define NRELS 8
#define KDIM  2048
#define EMAX  1048576
#define CMAX  50048
#define MAXM  50176

__device__ __align__(16) __half g_ah[(size_t)MAXM * KDIM];
__device__ __align__(16) __half g_al[(size_t)MAXM * KDIM];
__device__ __align__(16) __half g_bh[(size_t)DFEAT * KDIM];   // [n][k]
__device__ int   g_snode[EMAX];      // edge target nodes, rel-sorted per center
__device__ uint2 g_roff[CMAX];       // packed 8 x u8 relation start offsets

// ---------------------------------------------------------------------------
__device__ __forceinline__ uint32_t smem_u32(const void* p) {
    uint32_t a;
    asm("{ .reg .u64 t; cvta.to.shared.u64 t, %1; cvt.u32.u64 %0, t; }"
        : "=r"(a) : "l"(p));
    return a;
}
__device__ __forceinline__ void cp16(uint32_t dst, const void* src) {
    asm volatile("cp.async.cg.shared.global [%0], [%1], 16;"
                 :: "r"(dst), "l"(src));
}
__device__ __forceinline__ void ldm_x4(uint32_t& r0, uint32_t& r1,
                                       uint32_t& r2, uint32_t& r3, uint32_t a) {
    asm volatile("ldmatrix.sync.aligned.m8n8.x4.shared.b16 {%0,%1,%2,%3}, [%4];"
                 : "=r"(r0), "=r"(r1), "=r"(r2), "=r"(r3) : "r"(a));
}
__device__ __forceinline__ void mma_f16(float* c, const uint32_t* a,
                                        uint32_t b0, uint32_t b1) {
    asm volatile(
        "mma.sync.aligned.m16n8k16.row.col.f32.f16.f16.f32 "
        "{%0,%1,%2,%3}, {%4,%5,%6,%7}, {%8,%9}, {%0,%1,%2,%3};"
        : "+f"(c[0]), "+f"(c[1]), "+f"(c[2]), "+f"(c[3])
        : "r"(a[0]), "r"(a[1]), "r"(a[2]), "r"(a[3]), "r"(b0), "r"(b1));
}

// ---------------------------------------------------------------------------
// Phase 0a: weight transpose to fp16
// ---------------------------------------------------------------------------
__global__ void __launch_bounds__(256) wsplit_kernel(const float* __restrict__ w) {
    int i = blockIdx.x * 256 + threadIdx.x;   // over 256*2048
    int n = i >> 11;
    int k = i & 2047;
    g_bh[i] = __float2half(w[(size_t)k * DFEAT + n]);
}

// ---------------------------------------------------------------------------
// Phase 0b: per-center counting sort of edges by relation (1 thread/center)
// ---------------------------------------------------------------------------
__global__ void __launch_bounds__(256) sort_kernel(
    const int* __restrict__ ptr,
    const int* __restrict__ idx,
    const int* __restrict__ rel,
    int C)
{
    const int c = blockIdx.x * 256 + threadIdx.x;
    if (c >= C) return;
    const int beg = ptr[c];
    const int end = ptr[c + 1];

    int cnt[NRELS];
#pragma unroll
    for (int r = 0; r < NRELS; ++r) cnt[r] = 0;
    for (int e = beg; e < end; ++e) {
        const int re = __ldg(rel + e);
#pragma unroll
        for (int r = 0; r < NRELS; ++r) cnt[r] += (re == r);
    }
    int st[NRELS];
    int p = 0;
#pragma unroll
    for (int r = 0; r < NRELS; ++r) { st[r] = p; p += cnt[r]; }

    uint2 pk;
    pk.x = (uint32_t)st[0] | ((uint32_t)st[1] << 8) |
           ((uint32_t)st[2] << 16) | ((uint32_t)st[3] << 24);
    pk.y = (uint32_t)st[4] | ((uint32_t)st[5] << 8) |
           ((uint32_t)st[6] << 16) | ((uint32_t)st[7] << 24);
    g_roff[c] = pk;

    int pos[NRELS];
#pragma unroll
    for (int r = 0; r < NRELS; ++r) pos[r] = st[r];
    for (int e = beg; e < end; ++e) {
        const int re = __ldg(rel + e);
        int off = 0;
#pragma unroll
        for (int r = 0; r < NRELS; ++r) if (re == r) off = pos[r]++;
        g_snode[beg + off] = __ldg(idx + e);
    }
}

// ---------------------------------------------------------------------------
// Phase 1: aggregation over sorted runs -> fp16 hi/lo.
// 1 block = 1 center, 128 threads = 2 features each; run loops are
// warp-uniform (node-id loads broadcast through L1), no predication.
// ---------------------------------------------------------------------------
__global__ void __launch_bounds__(128) agg_kernel(
    const float* __restrict__ x,
    const int*   __restrict__ ptr,
    int C)
{
    const int c = blockIdx.x;
    if (c >= C) return;
    const int t   = threadIdx.x;
    const int beg = __ldg(ptr + c);
    const int deg = __ldg(ptr + c + 1) - beg;
    const uint2 ro = __ldg(&g_roff[c]);

    const size_t obase = (size_t)c * KDIM;
#pragma unroll
    for (int r = 0; r < NRELS; ++r) {
        const int js = (int)(((r < 4 ? ro.x : ro.y) >> ((r & 3) * 8)) & 0xFF);
        const int je = (r == 7) ? deg
            : (int)(((r + 1 < 4 ? ro.x : ro.y) >> (((r + 1) & 3) * 8)) & 0xFF);
        float ax = 0.f, ay = 0.f;
#pragma unroll 2
        for (int j = js; j < je; ++j) {
            const int nd = __ldg(&g_snode[beg + j]);
            const float2 v = __ldg((const float2*)(x + (size_t)nd * DFEAT) + t);
            ax += v.x; ay += v.y;
        }
        __half hx = __float2half(ax);
        __half hy = __float2half(ay);
        __half lx = __float2half(ax - __half2float(hx));
        __half ly = __float2half(ay - __half2float(hy));
        __half2 hh; hh.x = hx; hh.y = hy;
        __half2 ll; ll.x = lx; ll.y = ly;
        ((__half2*)(g_ah + obase + r * DFEAT))[t] = hh;
        ((__half2*)(g_al + obase + r * DFEAT))[t] = ll;
    }
}

// ---------------------------------------------------------------------------
// Phase 2: GEMM  out[M,256] = (Ah + Al)[M,2048] * Bt[256,2048]^T, / deg.
// CTA tile 128x128 (grid.y = 2), BK=32, 256 threads (8 warps of 64x32),
// double-buffered cp.async, 80B-padded smem rows (ldmatrix conflict-free).
// 2 MMA terms: Ah*Bh + Al*Bh.
// ---------------------------------------------------------------------------
#define BK     32
#define ROWB   80u
#define OFF_AH 0u
#define OFF_AL 10240u
#define OFF_B  20480u
#define STAGE  30720u
#define SMEMSZ (2u * STAGE)            // 61440 bytes

__global__ void __launch_bounds__(256, 2) gemm_kernel(
    const int* __restrict__ ptr,
    float*     __restrict__ out,
    int C)
{
    extern __shared__ char smem[];
    const uint32_t sbase = smem_u32(smem);
    const int tid  = threadIdx.x;
    const int lane = tid & 31;
    const int wid  = tid >> 5;
    const int bm   = blockIdx.x * 128;
    const int bn   = blockIdx.y * 128;

    const int warp_m = (wid & 1) * 64;
    const int warp_n = (wid >> 1) * 32;

    const __half* __restrict__ Ah = g_ah + (size_t)bm * KDIM;
    const __half* __restrict__ Al = g_al + (size_t)bm * KDIM;
    const __half* __restrict__ Bp = g_bh + (size_t)bn * KDIM;

    const int ch0_row = tid >> 2;          // rows 0..63
    const int ch1_row = (tid + 256) >> 2;  // rows 64..127
    const int ch_c    = tid & 3;

    float acc[4][4][4];
#pragma unroll
    for (int i = 0; i < 4; ++i)
#pragma unroll
        for (int j = 0; j < 4; ++j)
#pragma unroll
            for (int q = 0; q < 4; ++q) acc[i][j][q] = 0.f;

#define LOAD_STAGE(kt, buf)                                                     \
    do {                                                                        \
        const int      k0_ = (kt) * BK;                                         \
        const uint32_t sb_ = sbase + (uint32_t)(buf) * STAGE;                   \
        const uint32_t d0_ = (uint32_t)ch0_row * ROWB + ch_c * 16;              \
        const uint32_t d1_ = (uint32_t)ch1_row * ROWB + ch_c * 16;              \
        const size_t   o0_ = (size_t)ch0_row * KDIM + k0_ + ch_c * 8;           \
        const size_t   o1_ = (size_t)ch1_row * KDIM + k0_ + ch_c * 8;           \
        cp16(sb_ + OFF_AH + d0_, Ah + o0_);                                     \
        cp16(sb_ + OFF_AH + d1_, Ah + o1_);                                     \
        cp16(sb_ + OFF_AL + d0_, Al + o0_);                                     \
        cp16(sb_ + OFF_AL + d1_, Al + o1_);                                     \
        cp16(sb_ + OFF_B  + d0_, Bp + o0_);                                     \
        cp16(sb_ + OFF_B  + d1_, Bp + o1_);                                     \
        asm volatile("cp.async.commit_group;");                                 \
    } while (0)

    const uint32_t a_roff = (uint32_t)(warp_m + (lane & 15)) * ROWB +
                            (((uint32_t)lane >> 4) & 1) * 16;
    const uint32_t b_roff = (uint32_t)(warp_n + (((lane >> 4) & 1) * 8) + (lane & 7)) * ROWB +
                            (((uint32_t)lane >> 3) & 1) * 16;

    const int KT = KDIM / BK;      // 64
    LOAD_STAGE(0, 0);

    for (int kt = 0; kt < KT; ++kt) {
        const int buf = kt & 1;
        if (kt + 1 < KT) {
            LOAD_STAGE(kt + 1, buf ^ 1);
            asm volatile("cp.async.wait_group 1;");
        } else {
            asm volatile("cp.async.wait_group 0;");
        }
        __syncthreads();

        const uint32_t sb = sbase + (uint32_t)buf * STAGE;
#pragma unroll
        for (int kf = 0; kf < 2; ++kf) {
            const uint32_t kfo = (uint32_t)kf * 32;

            uint32_t ah[4][4], al[4][4], b[2][4];
#pragma unroll
            for (int mf = 0; mf < 4; ++mf)
                ldm_x4(ah[mf][0], ah[mf][1], ah[mf][2], ah[mf][3],
                       sb + OFF_AH + a_roff + (uint32_t)mf * 16 * ROWB + kfo);
#pragma unroll
            for (int np = 0; np < 2; ++np)
                ldm_x4(b[np][0], b[np][1], b[np][2], b[np][3],
                       sb + OFF_B + b_roff + (uint32_t)np * 16 * ROWB + kfo);

            // term 1: Ah * Bh
#pragma unroll
            for (int mf = 0; mf < 4; ++mf)
#pragma unroll
                for (int nf = 0; nf < 4; ++nf) {
                    const int s = (nf & 1) * 2;
                    mma_f16(acc[mf][nf], ah[mf], b[nf >> 1][s], b[nf >> 1][s + 1]);
                }

            // term 2: Al * Bh
#pragma unroll
            for (int mf = 0; mf < 4; ++mf)
                ldm_x4(al[mf][0], al[mf][1], al[mf][2], al[mf][3],
                       sb + OFF_AL + a_roff + (uint32_t)mf * 16 * ROWB + kfo);
#pragma unroll
            for (int mf = 0; mf < 4; ++mf)
#pragma unroll
                for (int nf = 0; nf < 4; ++nf) {
                    const int s = (nf & 1) * 2;
                    mma_f16(acc[mf][nf], al[mf], b[nf >> 1][s], b[nf >> 1][s + 1]);
                }
        }
        __syncthreads();
    }

    // epilogue: /deg, store
#pragma unroll
    for (int mf = 0; mf < 4; ++mf) {
        const int r0 = bm + warp_m + mf * 16 + (lane >> 2);
        const int r1 = r0 + 8;
        float inv0 = 0.f, inv1 = 0.f;
        if (r0 < C) inv0 = 1.f / (float)(__ldg(ptr + r0 + 1) - __ldg(ptr + r0));
        if (r1 < C) inv1 = 1.f / (float)(__ldg(ptr + r1 + 1) - __ldg(ptr + r1));
#pragma unroll
        for (int nf = 0; nf < 4; ++nf) {
            const int col = bn + warp_n + nf * 8 + (lane & 3) * 2;
            if (r0 < C) {
                float2 o; o.x = acc[mf][nf][0] * inv0; o.y = acc[mf][nf][1] * inv0;
                *(float2*)(out + (size_t)r0 * DFEAT + col) = o;
            }
            if (r1 < C) {
                float2 o; o.x = acc[mf][nf][2] * inv1; o.y = acc[mf][nf][3] * inv1;
                *(float2*)(out + (size_t)r1 * DFEAT + col) = o;
            }
        }
    }
}

// ---------------------------------------------------------------------------
extern "C" void kernel_launch(void* const* d_in, const int* in_sizes, int n_in,
                              void* d_out, int out_size) {
    const float* x   = (const float*)d_in[0];
    const float* w   = (const float*)d_in[1];
    const int*   ptr = (const int*)d_in[2];
    const int*   idx = (const int*)d_in[3];
    const int*   rel = (const int*)d_in[4];
    float*       out = (float*)d_out;

    const int C    = in_sizes[2] - 1;
    const int nblk = (C + 127) / 128;

    cudaFuncSetAttribute(gemm_kernel,
                         cudaFuncAttributeMaxDynamicSharedMemorySize, SMEMSZ);

    wsplit_kernel<<<(DFEAT * KDIM) / 256, 256>>>(w);
    sort_kernel<<<(C + 255) / 256, 256>>>(ptr, idx, rel, C);
    agg_kernel<<<C, 128>>>(x, ptr, C);

    dim3 grid(nblk, DFEAT / 128);
    gemm_kernel<<<grid, 256, SMEMSZ>>>(ptr, out, C);
}

// round 8
// speedup vs baseline: 2.1113x; 1.4953x over previous
#include <cuda_runtime.h>
#include <cuda_fp16.h>
#include <cstdint>

// ===========================================================================
// MyRGCNConv, single-term fp16:
//  Phase 0a: W[2048,256] f32 -> g_bh fp16, transposed [256 n][2048 k]
//  Phase 0b: per-center counting sort of edges by relation (g_snode, g_roff)
//  Phase 1:  agg over sorted runs -> A fp16
//  Phase 2:  out = (A*B) / deg   via m16n8k16 fp16 MMA, f32 accum
// ===========================================================================

#define DFEAT 256
#define NRELS 8
#define KDIM  2048
#define EMAX  1048576
#define CMAX  50048
#define MAXM  50176

__device__ __align__(16) __half g_ah[(size_t)MAXM * KDIM];
__device__ __align__(16) __half g_bh[(size_t)DFEAT * KDIM];   // [n][k]
__device__ int   g_snode[EMAX];      // edge target nodes, rel-sorted per center
__device__ uint2 g_roff[CMAX];       // packed 8 x u8 relation start offsets

// ---------------------------------------------------------------------------
__device__ __forceinline__ uint32_t smem_u32(const void* p) {
    uint32_t a;
    asm("{ .reg .u64 t; cvta.to.shared.u64 t, %1; cvt.u32.u64 %0, t; }"
        : "=r"(a) : "l"(p));
    return a;
}
__device__ __forceinline__ void cp16(uint32_t dst, const void* src) {
    asm volatile("cp.async.cg.shared.global [%0], [%1], 16;"
                 :: "r"(dst), "l"(src));
}
__device__ __forceinline__ void ldm_x4(uint32_t& r0, uint32_t& r1,
                                       uint32_t& r2, uint32_t& r3, uint32_t a) {
    asm volatile("ldmatrix.sync.aligned.m8n8.x4.shared.b16 {%0,%1,%2,%3}, [%4];"
                 : "=r"(r0), "=r"(r1), "=r"(r2), "=r"(r3) : "r"(a));
}
__device__ __forceinline__ void mma_f16(float* c, const uint32_t* a,
                                        uint32_t b0, uint32_t b1) {
    asm volatile(
        "mma.sync.aligned.m16n8k16.row.col.f32.f16.f16.f32 "
        "{%0,%1,%2,%3}, {%4,%5,%6,%7}, {%8,%9}, {%0,%1,%2,%3};"
        : "+f"(c[0]), "+f"(c[1]), "+f"(c[2]), "+f"(c[3])
        : "r"(a[0]), "r"(a[1]), "r"(a[2]), "r"(a[3]), "r"(b0), "r"(b1));
}

// ---------------------------------------------------------------------------
// Phase 0a: weight transpose to fp16
// ---------------------------------------------------------------------------
__global__ void __launch_bounds__(256) wsplit_kernel(const float* __restrict__ w) {
    int i = blockIdx.x * 256 + threadIdx.x;   // over 256*2048
    int n = i >> 11;
    int k = i & 2047;
    g_bh[i] = __float2half(w[(size_t)k * DFEAT + n]);
}

// ---------------------------------------------------------------------------
// Phase 0b: per-center counting sort of edges by relation (1 thread/center)
// ---------------------------------------------------------------------------
__global__ void __launch_bounds__(256) sort_kernel(
    const int* __restrict__ ptr,
    const int* __restrict__ idx,
    const int* __restrict__ rel,
    int C)
{
    const int c = blockIdx.x * 256 + threadIdx.x;
    if (c >= C) return;
    const int beg = ptr[c];
    const int end = ptr[c + 1];

    int cnt[NRELS];
#pragma unroll
    for (int r = 0; r < NRELS; ++r) cnt[r] = 0;
    for (int e = beg; e < end; ++e) {
        const int re = __ldg(rel + e);
#pragma unroll
        for (int r = 0; r < NRELS; ++r) cnt[r] += (re == r);
    }
    int st[NRELS];
    int p = 0;
#pragma unroll
    for (int r = 0; r < NRELS; ++r) { st[r] = p; p += cnt[r]; }

    uint2 pk;
    pk.x = (uint32_t)st[0] | ((uint32_t)st[1] << 8) |
           ((uint32_t)st[2] << 16) | ((uint32_t)st[3] << 24);
    pk.y = (uint32_t)st[4] | ((uint32_t)st[5] << 8) |
           ((uint32_t)st[6] << 16) | ((uint32_t)st[7] << 24);
    g_roff[c] = pk;

    int pos[NRELS];
#pragma unroll
    for (int r = 0; r < NRELS; ++r) pos[r] = st[r];
    for (int e = beg; e < end; ++e) {
        const int re = __ldg(rel + e);
        int off = 0;
#pragma unroll
        for (int r = 0; r < NRELS; ++r) if (re == r) off = pos[r]++;
        g_snode[beg + off] = __ldg(idx + e);
    }
}

// ---------------------------------------------------------------------------
// Phase 1: aggregation over sorted runs -> single fp16.
// 1 block = 1 center, 128 threads = 2 features each; run loops are
// warp-uniform (node-id loads broadcast through L1), no predication.
// ---------------------------------------------------------------------------
__global__ void __launch_bounds__(128) agg_kernel(
    const float* __restrict__ x,
    const int*   __restrict__ ptr,
    int C)
{
    const int c = blockIdx.x;
    if (c >= C) return;
    const int t   = threadIdx.x;
    const int beg = __ldg(ptr + c);
    const int deg = __ldg(ptr + c + 1) - beg;
    const uint2 ro = __ldg(&g_roff[c]);

    const size_t obase = (size_t)c * KDIM;
#pragma unroll
    for (int r = 0; r < NRELS; ++r) {
        const int js = (int)(((r < 4 ? ro.x : ro.y) >> ((r & 3) * 8)) & 0xFF);
        const int je = (r == 7) ? deg
            : (int)(((r + 1 < 4 ? ro.x : ro.y) >> (((r + 1) & 3) * 8)) & 0xFF);
        float ax = 0.f, ay = 0.f;
#pragma unroll 2
        for (int j = js; j < je; ++j) {
            const int nd = __ldg(&g_snode[beg + j]);
            const float2 v = __ldg((const float2*)(x + (size_t)nd * DFEAT) + t);
            ax += v.x; ay += v.y;
        }
        __half2 hh; hh.x = __float2half(ax); hh.y = __float2half(ay);
        ((__half2*)(g_ah + obase + r * DFEAT))[t] = hh;
    }
}

// ---------------------------------------------------------------------------
// Phase 2: GEMM  out[M,256] = A[M,2048] * Bt[256,2048]^T, / deg.
// CTA tile 128x128 (grid.y = 2), BK=32, 256 threads (8 warps of 64x32),
// double-buffered cp.async, 80B-padded smem rows (ldmatrix conflict-free).
// Single fp16 MMA term.
// ---------------------------------------------------------------------------
#define BK     32
#define ROWB   80u
#define OFF_A  0u
#define OFF_B  10240u
#define STAGE  20480u
#define SMEMSZ (2u * STAGE)            // 40960 bytes

__global__ void __launch_bounds__(256, 2) gemm_kernel(
    const int* __restrict__ ptr,
    float*     __restrict__ out,
    int C)
{
    extern __shared__ char smem[];
    const uint32_t sbase = smem_u32(smem);
    const int tid  = threadIdx.x;
    const int lane = tid & 31;
    const int wid  = tid >> 5;
    const int bm   = blockIdx.x * 128;
    const int bn   = blockIdx.y * 128;

    const int warp_m = (wid & 1) * 64;
    const int warp_n = (wid >> 1) * 32;

    const __half* __restrict__ Ap = g_ah + (size_t)bm * KDIM;
    const __half* __restrict__ Bp = g_bh + (size_t)bn * KDIM;

    const int ch0_row = tid >> 2;          // rows 0..63
    const int ch1_row = (tid + 256) >> 2;  // rows 64..127
    const int ch_c    = tid & 3;

    float acc[4][4][4];
#pragma unroll
    for (int i = 0; i < 4; ++i)
#pragma unroll
        for (int j = 0; j < 4; ++j)
#pragma unroll
            for (int q = 0; q < 4; ++q) acc[i][j][q] = 0.f;

#define LOAD_STAGE(kt, buf)                                                     \
    do {                                                                        \
        const int      k0_ = (kt) * BK;                                         \
        const uint32_t sb_ = sbase + (uint32_t)(buf) * STAGE;                   \
        const uint32_t d0_ = (uint32_t)ch0_row * ROWB + ch_c * 16;              \
        const uint32_t d1_ = (uint32_t)ch1_row * ROWB + ch_c * 16;              \
        const size_t   o0_ = (size_t)ch0_row * KDIM + k0_ + ch_c * 8;           \
        const size_t   o1_ = (size_t)ch1_row * KDIM + k0_ + ch_c * 8;           \
        cp16(sb_ + OFF_A + d0_, Ap + o0_);                                      \
        cp16(sb_ + OFF_A + d1_, Ap + o1_);                                      \
        cp16(sb_ + OFF_B + d0_, Bp + o0_);                                      \
        cp16(sb_ + OFF_B + d1_, Bp + o1_);                                      \
        asm volatile("cp.async.commit_group;");                                 \
    } while (0)

    const uint32_t a_roff = (uint32_t)(warp_m + (lane & 15)) * ROWB +
                            (((uint32_t)lane >> 4) & 1) * 16;
    const uint32_t b_roff = (uint32_t)(warp_n + (((lane >> 4) & 1) * 8) + (lane & 7)) * ROWB +
                            (((uint32_t)lane >> 3) & 1) * 16;

    const int KT = KDIM / BK;      // 64
    LOAD_STAGE(0, 0);

    for (int kt = 0; kt < KT; ++kt) {
        const int buf = kt & 1;
        if (kt + 1 < KT) {
            LOAD_STAGE(kt + 1, buf ^ 1);
            asm volatile("cp.async.wait_group 1;");
        } else {
            asm volatile("cp.async.wait_group 0;");
        }
        __syncthreads();

        const uint32_t sb = sbase + (uint32_t)buf * STAGE;
#pragma unroll
        for (int kf = 0; kf < 2; ++kf) {
            const uint32_t kfo = (uint32_t)kf * 32;

            uint32_t a[4][4], b[2][4];
#pragma unroll
            for (int mf = 0; mf < 4; ++mf)
                ldm_x4(a[mf][0], a[mf][1], a[mf][2], a[mf][3],
                       sb + OFF_A + a_roff + (uint32_t)mf * 16 * ROWB + kfo);
#pragma unroll
            for (int np = 0; np < 2; ++np)
                ldm_x4(b[np][0], b[np][1], b[np][2], b[np][3],
                       sb + OFF_B + b_roff + (uint32_t)np * 16 * ROWB + kfo);

#pragma unroll
            for (int mf = 0; mf < 4; ++mf)
#pragma unroll
                for (int nf = 0; nf < 4; ++nf) {
                    const int s = (nf & 1) * 2;
                    mma_f16(acc[mf][nf], a[mf], b[nf >> 1][s], b[nf >> 1][s + 1]);
                }
        }
        __syncthreads();
    }

    // epilogue: /deg, store
#pragma unroll
    for (int mf = 0; mf < 4; ++mf) {
        const int r0 = bm + warp_m + mf * 16 + (lane >> 2);
        const int r1 = r0 + 8;
        float inv0 = 0.f, inv1 = 0.f;
        if (r0 < C) inv0 = 1.f / (float)(__ldg(ptr + r0 + 1) - __ldg(ptr + r0));
        if (r1 < C) inv1 = 1.f / (float)(__ldg(ptr + r1 + 1) - __ldg(ptr + r1));
#pragma unroll
        for (int nf = 0; nf < 4; ++nf) {
            const int col = bn + warp_n + nf * 8 + (lane & 3) * 2;
            if (r0 < C) {
                float2 o; o.x = acc[mf][nf][0] * inv0; o.y = acc[mf][nf][1] * inv0;
                *(float2*)(out + (size_t)r0 * DFEAT + col) = o;
            }
            if (r1 < C) {
                float2 o; o.x = acc[mf][nf][2] * inv1; o.y = acc[mf][nf][3] * inv1;
                *(float2*)(out + (size_t)r1 * DFEAT + col) = o;
            }
        }
    }
}

// ---------------------------------------------------------------------------
extern "C" void kernel_launch(void* const* d_in, const int* in_sizes, int n_in,
                              void* d_out, int out_size) {
    const float* x   = (const float*)d_in[0];
    const float* w   = (const float*)d_in[1];
    const int*   ptr = (const int*)d_in[2];
    const int*   idx = (const int*)d_in[3];
    const int*   rel = (const int*)d_in[4];
    float*       out = (float*)d_out;

    const int C    = in_sizes[2] - 1;
    const int nblk = (C + 127) / 128;

    cudaFuncSetAttribute(gemm_kernel,
                         cudaFuncAttributeMaxDynamicSharedMemorySize, SMEMSZ);

    wsplit_kernel<<<(DFEAT * KDIM) / 256, 256>>>(w);
    sort_kernel<<<(C + 255) / 256, 256>>>(ptr, idx, rel, C);
    agg_kernel<<<C, 128>>>(x, ptr, C);

    dim3 grid(nblk, DFEAT / 128);
    gemm_kernel<<<grid, 256, SMEMSZ>>>(ptr, out, C);
}

// round 9
// speedup vs baseline: 2.1502x; 1.0184x over previous
#include <cuda_runtime.h>
#include <cuda_fp16.h>
#include <cstdint>

// ===========================================================================
// MyRGCNConv, single-term fp16, fp16-gather agg, 3-stage GEMM pipeline:
//  Phase 0a: W[2048,256] f32 -> g_bh fp16, transposed [256 n][2048 k]
//  Phase 0b: x f32 -> g_xh fp16 (halves gather traffic)
//  Phase 0c: per-center counting sort of edges by relation (g_snode, g_roff)
//  Phase 1:  agg over sorted runs (fp16 gather, fp32 accum) -> A fp16
//  Phase 2:  out = (A*B) / deg   via m16n8k16 fp16 MMA, f32 accum
// ===========================================================================

#define DFEAT 256
#define NRELS 8
#define KDIM  2048
#define EMAX  1048576
#define CMAX  50048
#define MAXM  50176
#define NMAX  50176

__device__ __align__(16) __half g_ah[(size_t)MAXM * KDIM];
__device__ __align__(16) __half g_bh[(size_t)DFEAT * KDIM];   // [n][k]
__device__ __align__(16) __half g_xh[(size_t)NMAX * DFEAT];   // fp16 copy of x
__device__ int   g_snode[EMAX];      // edge target nodes, rel-sorted per center
__device__ uint2 g_roff[CMAX];       // packed 8 x u8 relation start offsets

// ---------------------------------------------------------------------------
__device__ __forceinline__ uint32_t smem_u32(const void* p) {
    uint32_t a;
    asm("{ .reg .u64 t; cvta.to.shared.u64 t, %1; cvt.u32.u64 %0, t; }"
        : "=r"(a) : "l"(p));
    return a;
}
__device__ __forceinline__ void cp16(uint32_t dst, const void* src) {
    asm volatile("cp.async.cg.shared.global [%0], [%1], 16;"
                 :: "r"(dst), "l"(src));
}
__device__ __forceinline__ void ldm_x4(uint32_t& r0, uint32_t& r1,
                                       uint32_t& r2, uint32_t& r3, uint32_t a) {
    asm volatile("ldmatrix.sync.aligned.m8n8.x4.shared.b16 {%0,%1,%2,%3}, [%4];"
                 : "=r"(r0), "=r"(r1), "=r"(r2), "=r"(r3) : "r"(a));
}
__device__ __forceinline__ void mma_f16(float* c, const uint32_t* a,
                                        uint32_t b0, uint32_t b1) {
    asm volatile(
        "mma.sync.aligned.m16n8k16.row.col.f32.f16.f16.f32 "
        "{%0,%1,%2,%3}, {%4,%5,%6,%7}, {%8,%9}, {%0,%1,%2,%3};"
        : "+f"(c[0]), "+f"(c[1]), "+f"(c[2]), "+f"(c[3])
        : "r"(a[0]), "r"(a[1]), "r"(a[2]), "r"(a[3]), "r"(b0), "r"(b1));
}

// ---------------------------------------------------------------------------
// Phase 0a: weight transpose to fp16
// ---------------------------------------------------------------------------
__global__ void __launch_bounds__(256) wsplit_kernel(const float* __restrict__ w) {
    int i = blockIdx.x * 256 + threadIdx.x;   // over 256*2048
    int n = i >> 11;
    int k = i & 2047;
    g_bh[i] = __float2half(w[(size_t)k * DFEAT + n]);
}

// ---------------------------------------------------------------------------
// Phase 0b: x f32 -> fp16 (elementwise, 2 per thread)
// ---------------------------------------------------------------------------
__global__ void __launch_bounds__(256) xconv_kernel(const float* __restrict__ x,
                                                    int n2) {
    int i = blockIdx.x * 256 + threadIdx.x;
    if (i >= n2) return;
    const float2 v = ((const float2*)x)[i];
    __half2 h; h.x = __float2half(v.x); h.y = __float2half(v.y);
    ((__half2*)g_xh)[i] = h;
}

// ---------------------------------------------------------------------------
// Phase 0c: per-center counting sort of edges by relation (1 thread/center)
// ---------------------------------------------------------------------------
__global__ void __launch_bounds__(256) sort_kernel(
    const int* __restrict__ ptr,
    const int* __restrict__ idx,
    const int* __restrict__ rel,
    int C)
{
    const int c = blockIdx.x * 256 + threadIdx.x;
    if (c >= C) return;
    const int beg = ptr[c];
    const int end = ptr[c + 1];

    int cnt[NRELS];
#pragma unroll
    for (int r = 0; r < NRELS; ++r) cnt[r] = 0;
    for (int e = beg; e < end; ++e) {
        const int re = __ldg(rel + e);
#pragma unroll
        for (int r = 0; r < NRELS; ++r) cnt[r] += (re == r);
    }
    int st[NRELS];
    int p = 0;
#pragma unroll
    for (int r = 0; r < NRELS; ++r) { st[r] = p; p += cnt[r]; }

    uint2 pk;
    pk.x = (uint32_t)st[0] | ((uint32_t)st[1] << 8) |
           ((uint32_t)st[2] << 16) | ((uint32_t)st[3] << 24);
    pk.y = (uint32_t)st[4] | ((uint32_t)st[5] << 8) |
           ((uint32_t)st[6] << 16) | ((uint32_t)st[7] << 24);
    g_roff[c] = pk;

    int pos[NRELS];
#pragma unroll
    for (int r = 0; r < NRELS; ++r) pos[r] = st[r];
    for (int e = beg; e < end; ++e) {
        const int re = __ldg(rel + e);
        int off = 0;
#pragma unroll
        for (int r = 0; r < NRELS; ++r) if (re == r) off = pos[r]++;
        g_snode[beg + off] = __ldg(idx + e);
    }
}

// ---------------------------------------------------------------------------
// Phase 1: aggregation over sorted runs, fp16 gather -> fp32 accum -> fp16.
// 1 block = 1 center, 128 threads = 2 features each (half2 = 4B per gather).
// ---------------------------------------------------------------------------
__global__ void __launch_bounds__(128) agg_kernel(
    const int* __restrict__ ptr,
    int C)
{
    const int c = blockIdx.x;
    if (c >= C) return;
    const int t   = threadIdx.x;
    const int beg = __ldg(ptr + c);
    const int deg = __ldg(ptr + c + 1) - beg;
    const uint2 ro = __ldg(&g_roff[c]);

    const size_t obase = (size_t)c * KDIM;
#pragma unroll
    for (int r = 0; r < NRELS; ++r) {
        const int js = (int)(((r < 4 ? ro.x : ro.y) >> ((r & 3) * 8)) & 0xFF);
        const int je = (r == 7) ? deg
            : (int)(((r + 1 < 4 ? ro.x : ro.y) >> (((r + 1) & 3) * 8)) & 0xFF);
        float ax = 0.f, ay = 0.f;
#pragma unroll 2
        for (int j = js; j < je; ++j) {
            const int nd = __ldg(&g_snode[beg + j]);
            const __half2 v = ((const __half2*)(g_xh + (size_t)nd * DFEAT))[t];
            const float2 vf = __half22float2(v);
            ax += vf.x; ay += vf.y;
        }
        __half2 hh; hh.x = __float2half(ax); hh.y = __float2half(ay);
        ((__half2*)(g_ah + obase + r * DFEAT))[t] = hh;
    }
}

// ---------------------------------------------------------------------------
// Phase 2: GEMM  out[M,256] = A[M,2048] * Bt[256,2048]^T, / deg.
// CTA tile 128x128 (grid.y = 2), BK=32, 256 threads (8 warps of 64x32),
// 3-stage cp.async pipeline with ONE __syncthreads per K-iteration.
// 80B-padded smem rows (ldmatrix conflict-free).
// ---------------------------------------------------------------------------
#define BK     32
#define ROWB   80u
#define OFF_A  0u
#define OFF_B  10240u
#define STAGE  20480u
#define NSTG   3
#define SMEMSZ (NSTG * STAGE)          // 61440 bytes

__global__ void __launch_bounds__(256, 2) gemm_kernel(
    const int* __restrict__ ptr,
    float*     __restrict__ out,
    int C)
{
    extern __shared__ char smem[];
    const uint32_t sbase = smem_u32(smem);
    const int tid  = threadIdx.x;
    const int lane = tid & 31;
    const int wid  = tid >> 5;
    const int bm   = blockIdx.x * 128;
    const int bn   = blockIdx.y * 128;

    const int warp_m = (wid & 1) * 64;
    const int warp_n = (wid >> 1) * 32;

    const __half* __restrict__ Ap = g_ah + (size_t)bm * KDIM;
    const __half* __restrict__ Bp = g_bh + (size_t)bn * KDIM;

    const int ch0_row = tid >> 2;          // rows 0..63
    const int ch1_row = (tid + 256) >> 2;  // rows 64..127
    const int ch_c    = tid & 3;

    float acc[4][4][4];
#pragma unroll
    for (int i = 0; i < 4; ++i)
#pragma unroll
        for (int j = 0; j < 4; ++j)
#pragma unroll
            for (int q = 0; q < 4; ++q) acc[i][j][q] = 0.f;

#define LOAD_STAGE(kt, buf)                                                     \
    do {                                                                        \
        const int      k0_ = (kt) * BK;                                         \
        const uint32_t sb_ = sbase + (uint32_t)(buf) * STAGE;                   \
        const uint32_t d0_ = (uint32_t)ch0_row * ROWB + ch_c * 16;              \
        const uint32_t d1_ = (uint32_t)ch1_row * ROWB + ch_c * 16;              \
        const size_t   o0_ = (size_t)ch0_row * KDIM + k0_ + ch_c * 8;           \
        const size_t   o1_ = (size_t)ch1_row * KDIM + k0_ + ch_c * 8;           \
        cp16(sb_ + OFF_A + d0_, Ap + o0_);                                      \
        cp16(sb_ + OFF_A + d1_, Ap + o1_);                                      \
        cp16(sb_ + OFF_B + d0_, Bp + o0_);                                      \
        cp16(sb_ + OFF_B + d1_, Bp + o1_);                                      \
        asm volatile("cp.async.commit_group;");                                 \
    } while (0)

    const uint32_t a_roff = (uint32_t)(warp_m + (lane & 15)) * ROWB +
                            (((uint32_t)lane >> 4) & 1) * 16;
    const uint32_t b_roff = (uint32_t)(warp_n + (((lane >> 4) & 1) * 8) + (lane & 7)) * ROWB +
                            (((uint32_t)lane >> 3) & 1) * 16;

    const int KT = KDIM / BK;      // 64
    LOAD_STAGE(0, 0);
    LOAD_STAGE(1, 1);

    int buf = 0;                   // stage holding kt's data
    for (int kt = 0; kt < KT; ++kt) {
        if (kt == KT - 1) {
            asm volatile("cp.async.wait_group 0;");
        } else {
            asm volatile("cp.async.wait_group 1;");
        }
        __syncthreads();           // all warps done with stage (kt-1)%3

        if (kt + 2 < KT) {
            const int nbuf = (buf + 2 >= NSTG) ? buf + 2 - NSTG : buf + 2;
            LOAD_STAGE(kt + 2, nbuf);
        }

        const uint32_t sb = sbase + (uint32_t)buf * STAGE;
#pragma unroll
        for (int kf = 0; kf < 2; ++kf) {
            const uint32_t kfo = (uint32_t)kf * 32;

            uint32_t a[4][4], b[2][4];
#pragma unroll
            for (int mf = 0; mf < 4; ++mf)
                ldm_x4(a[mf][0], a[mf][1], a[mf][2], a[mf][3],
                       sb + OFF_A + a_roff + (uint32_t)mf * 16 * ROWB + kfo);
#pragma unroll
            for (int np = 0; np < 2; ++np)
                ldm_x4(b[np][0], b[np][1], b[np][2], b[np][3],
                       sb + OFF_B + b_roff + (uint32_t)np * 16 * ROWB + kfo);

#pragma unroll
            for (int mf = 0; mf < 4; ++mf)
#pragma unroll
                for (int nf = 0; nf < 4; ++nf) {
                    const int s = (nf & 1) * 2;
                    mma_f16(acc[mf][nf], a[mf], b[nf >> 1][s], b[nf >> 1][s + 1]);
                }
        }
        buf = (buf + 1 >= NSTG) ? 0 : buf + 1;
    }

    // epilogue: /deg, store
#pragma unroll
    for (int mf = 0; mf < 4; ++mf) {
        const int r0 = bm + warp_m + mf * 16 + (lane >> 2);
        const int r1 = r0 + 8;
        float inv0 = 0.f, inv1 = 0.f;
        if (r0 < C) inv0 = 1.f / (float)(__ldg(ptr + r0 + 1) - __ldg(ptr + r0));
        if (r1 < C) inv1 = 1.f / (float)(__ldg(ptr + r1 + 1) - __ldg(ptr + r1));
#pragma unroll
        for (int nf = 0; nf < 4; ++nf) {
            const int col = bn + warp_n + nf * 8 + (lane & 3) * 2;
            if (r0 < C) {
                float2 o; o.x = acc[mf][nf][0] * inv0; o.y = acc[mf][nf][1] * inv0;
                *(float2*)(out + (size_t)r0 * DFEAT + col) = o;
            }
            if (r1 < C) {
                float2 o; o.x = acc[mf][nf][2] * inv1; o.y = acc[mf][nf][3] * inv1;
                *(float2*)(out + (size_t)r1 * DFEAT + col) = o;
            }
        }
    }
}

// ---------------------------------------------------------------------------
extern "C" void kernel_launch(void* const* d_in, const int* in_sizes, int n_in,
                              void* d_out, int out_size) {
    const float* x   = (const float*)d_in[0];
    const float* w   = (const float*)d_in[1];
    const int*   ptr = (const int*)d_in[2];
    const int*   idx = (const int*)d_in[3];
    const int*   rel = (const int*)d_in[4];
    float*       out = (float*)d_out;

    const int C    = in_sizes[2] - 1;
    const int nblk = (C + 127) / 128;
    const int xn2  = in_sizes[0] / 2;      // half2 count of x

    cudaFuncSetAttribute(gemm_kernel,
                         cudaFuncAttributeMaxDynamicSharedMemorySize, SMEMSZ);

    wsplit_kernel<<<(DFEAT * KDIM) / 256, 256>>>(w);
    xconv_kernel<<<(xn2 + 255) / 256, 256>>>(x, xn2);
    sort_kernel<<<(C + 255) / 256, 256>>>(ptr, idx, rel, C);
    agg_kernel<<<C, 128>>>(ptr, C);

    dim3 grid(nblk, DFEAT / 128);
    gemm_kernel<<<grid, 256, SMEMSZ>>>(ptr, out, C);
}

// round 10
// speedup vs baseline: 2.5419x; 1.1822x over previous
#include <cuda_runtime.h>
#include <cuda_fp16.h>
#include <cstdint>

// ===========================================================================
// MyRGCNConv, single-term fp16:
//  Phase 0a: W[2048,256] f32 -> g_bh fp16, transposed [256 n][2048 k]
//  Phase 0b: x f32 -> g_xh fp16
//  Phase 0c: per-center counting sort of edges by relation; g_snode holds
//            pre-scaled element offsets (node * 256)
//  Phase 1:  agg, warp-per-center, LDG.128 row gather, fp32 accum -> A fp16
//  Phase 2:  out = (A*B) / deg  via m16n8k16 fp16 MMA, 4-stage cp.async pipe
// ===========================================================================

#define DFEAT 256
#define NRELS 8
#define KDIM  2048
#define EMAX  1048576
#define CMAX  50048
#define MAXM  50176
#define NMAX  50176

__device__ __align__(16) __half g_ah[(size_t)MAXM * KDIM];
__device__ __align__(16) __half g_bh[(size_t)DFEAT * KDIM];   // [n][k]
__device__ __align__(16) __half g_xh[(size_t)NMAX * DFEAT];   // fp16 copy of x
__device__ int   g_snode[EMAX];      // element offsets (node*256), rel-sorted
__device__ uint2 g_roff[CMAX];       // packed 8 x u8 relation start offsets

// ---------------------------------------------------------------------------
__device__ __forceinline__ uint32_t smem_u32(const void* p) {
    uint32_t a;
    asm("{ .reg .u64 t; cvta.to.shared.u64 t, %1; cvt.u32.u64 %0, t; }"
        : "=r"(a) : "l"(p));
    return a;
}
__device__ __forceinline__ void cp16(uint32_t dst, const void* src) {
    asm volatile("cp.async.cg.shared.global [%0], [%1], 16;"
                 :: "r"(dst), "l"(src));
}
__device__ __forceinline__ void ldm_x4(uint32_t& r0, uint32_t& r1,
                                       uint32_t& r2, uint32_t& r3, uint32_t a) {
    asm volatile("ldmatrix.sync.aligned.m8n8.x4.shared.b16 {%0,%1,%2,%3}, [%4];"
                 : "=r"(r0), "=r"(r1), "=r"(r2), "=r"(r3) : "r"(a));
}
__device__ __forceinline__ void mma_f16(float* c, const uint32_t* a,
                                        uint32_t b0, uint32_t b1) {
    asm volatile(
        "mma.sync.aligned.m16n8k16.row.col.f32.f16.f16.f32 "
        "{%0,%1,%2,%3}, {%4,%5,%6,%7}, {%8,%9}, {%0,%1,%2,%3};"
        : "+f"(c[0]), "+f"(c[1]), "+f"(c[2]), "+f"(c[3])
        : "r"(a[0]), "r"(a[1]), "r"(a[2]), "r"(a[3]), "r"(b0), "r"(b1));
}

// ---------------------------------------------------------------------------
// Phase 0a: weight transpose to fp16
// ---------------------------------------------------------------------------
__global__ void __launch_bounds__(256) wsplit_kernel(const float* __restrict__ w) {
    int i = blockIdx.x * 256 + threadIdx.x;   // over 256*2048
    int n = i >> 11;
    int k = i & 2047;
    g_bh[i] = __float2half(w[(size_t)k * DFEAT + n]);
}

// ---------------------------------------------------------------------------
// Phase 0b: x f32 -> fp16
// ---------------------------------------------------------------------------
__global__ void __launch_bounds__(256) xconv_kernel(const float* __restrict__ x,
                                                    int n2) {
    int i = blockIdx.x * 256 + threadIdx.x;
    if (i >= n2) return;
    const float2 v = ((const float2*)x)[i];
    __half2 h; h.x = __float2half(v.x); h.y = __float2half(v.y);
    ((__half2*)g_xh)[i] = h;
}

// ---------------------------------------------------------------------------
// Phase 0c: per-center counting sort by relation; emit element offsets
// ---------------------------------------------------------------------------
__global__ void __launch_bounds__(256) sort_kernel(
    const int* __restrict__ ptr,
    const int* __restrict__ idx,
    const int* __restrict__ rel,
    int C)
{
    const int c = blockIdx.x * 256 + threadIdx.x;
    if (c >= C) return;
    const int beg = ptr[c];
    const int end = ptr[c + 1];

    int cnt[NRELS];
#pragma unroll
    for (int r = 0; r < NRELS; ++r) cnt[r] = 0;
    for (int e = beg; e < end; ++e) {
        const int re = __ldg(rel + e);
#pragma unroll
        for (int r = 0; r < NRELS; ++r) cnt[r] += (re == r);
    }
    int st[NRELS];
    int p = 0;
#pragma unroll
    for (int r = 0; r < NRELS; ++r) { st[r] = p; p += cnt[r]; }

    uint2 pk;
    pk.x = (uint32_t)st[0] | ((uint32_t)st[1] << 8) |
           ((uint32_t)st[2] << 16) | ((uint32_t)st[3] << 24);
    pk.y = (uint32_t)st[4] | ((uint32_t)st[5] << 8) |
           ((uint32_t)st[6] << 16) | ((uint32_t)st[7] << 24);
    g_roff[c] = pk;

    int pos[NRELS];
#pragma unroll
    for (int r = 0; r < NRELS; ++r) pos[r] = st[r];
    for (int e = beg; e < end; ++e) {
        const int re = __ldg(rel + e);
        int off = 0;
#pragma unroll
        for (int r = 0; r < NRELS; ++r) if (re == r) off = pos[r]++;
        g_snode[beg + off] = __ldg(idx + e) << 8;   // pre-scaled (x256)
    }
}

// ---------------------------------------------------------------------------
// Phase 1: aggregation, warp-per-center. Lane owns 8 features (16 B).
// One LDG.128 per edge per warp covers the full 512-byte fp16 row.
// ---------------------------------------------------------------------------
__global__ void __launch_bounds__(128) agg_kernel(
    const int* __restrict__ ptr,
    int C)
{
    const int warp = threadIdx.x >> 5;
    const int lane = threadIdx.x & 31;
    const int c = blockIdx.x * 4 + warp;
    if (c >= C) return;

    const int beg = __ldg(ptr + c);
    const int deg = __ldg(ptr + c + 1) - beg;
    const uint2 ro = __ldg(&g_roff[c]);
    const int fo = lane * 8;                       // feature offset (halves)
    const size_t obase = (size_t)c * KDIM;

#pragma unroll
    for (int r = 0; r < NRELS; ++r) {
        const int js = (int)(((r < 4 ? ro.x : ro.y) >> ((r & 3) * 8)) & 0xFF);
        const int je = (r == 7) ? deg
            : (int)(((r + 1 < 4 ? ro.x : ro.y) >> (((r + 1) & 3) * 8)) & 0xFF);
        float s0 = 0.f, s1 = 0.f, s2 = 0.f, s3 = 0.f;
        float s4 = 0.f, s5 = 0.f, s6 = 0.f, s7 = 0.f;
#pragma unroll 2
        for (int j = js; j < je; ++j) {
            const int off = __ldg(&g_snode[beg + j]);     // node*256, uniform
            const uint4 v = __ldg((const uint4*)(g_xh + off + fo));
            const float2 f0 = __half22float2(*(const __half2*)&v.x);
            const float2 f1 = __half22float2(*(const __half2*)&v.y);
            const float2 f2 = __half22float2(*(const __half2*)&v.z);
            const float2 f3 = __half22float2(*(const __half2*)&v.w);
            s0 += f0.x; s1 += f0.y; s2 += f1.x; s3 += f1.y;
            s4 += f2.x; s5 += f2.y; s6 += f3.x; s7 += f3.y;
        }
        __half2 h0, h1, h2, h3;
        h0.x = __float2half(s0); h0.y = __float2half(s1);
        h1.x = __float2half(s2); h1.y = __float2half(s3);
        h2.x = __float2half(s4); h2.y = __float2half(s5);
        h3.x = __float2half(s6); h3.y = __float2half(s7);
        uint4 o;
        o.x = *(uint32_t*)&h0; o.y = *(uint32_t*)&h1;
        o.z = *(uint32_t*)&h2; o.w = *(uint32_t*)&h3;
        *(uint4*)(g_ah + obase + r * DFEAT + fo) = o;
    }
}

// ---------------------------------------------------------------------------
// Phase 2: GEMM  out[M,256] = A[M,2048] * Bt[256,2048]^T, / deg.
// CTA tile 128x128 (grid.y = 2), BK=32, 256 threads (8 warps of 64x32),
// 4-stage cp.async pipeline, one __syncthreads per K-iteration.
// 80B-padded smem rows (ldmatrix conflict-free).
// ---------------------------------------------------------------------------
#define BK     32
#define ROWB   80u
#define OFF_A  0u
#define OFF_B  10240u
#define STAGE  20480u
#define NSTG   4
#define SMEMSZ (NSTG * STAGE)          // 81920 bytes

__global__ void __launch_bounds__(256, 2) gemm_kernel(
    const int* __restrict__ ptr,
    float*     __restrict__ out,
    int C)
{
    extern __shared__ char smem[];
    const uint32_t sbase = smem_u32(smem);
    const int tid  = threadIdx.x;
    const int lane = tid & 31;
    const int wid  = tid >> 5;
    const int bm   = blockIdx.x * 128;
    const int bn   = blockIdx.y * 128;

    const int warp_m = (wid & 1) * 64;
    const int warp_n = (wid >> 1) * 32;

    const __half* __restrict__ Ap = g_ah + (size_t)bm * KDIM;
    const __half* __restrict__ Bp = g_bh + (size_t)bn * KDIM;

    const int ch0_row = tid >> 2;          // rows 0..63
    const int ch1_row = (tid + 256) >> 2;  // rows 64..127
    const int ch_c    = tid & 3;

    float acc[4][4][4];
#pragma unroll
    for (int i = 0; i < 4; ++i)
#pragma unroll
        for (int j = 0; j < 4; ++j)
#pragma unroll
            for (int q = 0; q < 4; ++q) acc[i][j][q] = 0.f;

#define LOAD_STAGE(kt, buf)                                                     \
    do {                                                                        \
        const int      k0_ = (kt) * BK;                                         \
        const uint32_t sb_ = sbase + (uint32_t)(buf) * STAGE;                   \
        const uint32_t d0_ = (uint32_t)ch0_row * ROWB + ch_c * 16;              \
        const uint32_t d1_ = (uint32_t)ch1_row * ROWB + ch_c * 16;              \
        const size_t   o0_ = (size_t)ch0_row * KDIM + k0_ + ch_c * 8;           \
        const size_t   o1_ = (size_t)ch1_row * KDIM + k0_ + ch_c * 8;           \
        cp16(sb_ + OFF_A + d0_, Ap + o0_);                                      \
        cp16(sb_ + OFF_A + d1_, Ap + o1_);                                      \
        cp16(sb_ + OFF_B + d0_, Bp + o0_);                                      \
        cp16(sb_ + OFF_B + d1_, Bp + o1_);                                      \
        asm volatile("cp.async.commit_group;");                                 \
    } while (0)

    const uint32_t a_roff = (uint32_t)(warp_m + (lane & 15)) * ROWB +
                            (((uint32_t)lane >> 4) & 1) * 16;
    const uint32_t b_roff = (uint32_t)(warp_n + (((lane >> 4) & 1) * 8) + (lane & 7)) * ROWB +
                            (((uint32_t)lane >> 3) & 1) * 16;

    const int KT = KDIM / BK;      // 64
    LOAD_STAGE(0, 0);
    LOAD_STAGE(1, 1);
    LOAD_STAGE(2, 2);

    for (int kt = 0; kt < KT; ++kt) {
        // ensure stage kt's group has completed (groups complete in order)
        if (kt < KT - 2) {
            asm volatile("cp.async.wait_group 2;");
        } else if (kt == KT - 2) {
            asm volatile("cp.async.wait_group 1;");
        } else {
            asm volatile("cp.async.wait_group 0;");
        }
        __syncthreads();           // all warps done consuming stage (kt-1)%4

        if (kt + 3 < KT) {
            const int nbuf = (kt + 3) & 3;
            LOAD_STAGE(kt + 3, nbuf);
        }

        const uint32_t sb = sbase + (uint32_t)(kt & 3) * STAGE;
#pragma unroll
        for (int kf = 0; kf < 2; ++kf) {
            const uint32_t kfo = (uint32_t)kf * 32;

            uint32_t a[4][4], b[2][4];
#pragma unroll
            for (int mf = 0; mf < 4; ++mf)
                ldm_x4(a[mf][0], a[mf][1], a[mf][2], a[mf][3],
                       sb + OFF_A + a_roff + (uint32_t)mf * 16 * ROWB + kfo);
#pragma unroll
            for (int np = 0; np < 2; ++np)
                ldm_x4(b[np][0], b[np][1], b[np][2], b[np][3],
                       sb + OFF_B + b_roff + (uint32_t)np * 16 * ROWB + kfo);

#pragma unroll
            for (int mf = 0; mf < 4; ++mf)
#pragma unroll
                for (int nf = 0; nf < 4; ++nf) {
                    const int s = (nf & 1) * 2;
                    mma_f16(acc[mf][nf], a[mf], b[nf >> 1][s], b[nf >> 1][s + 1]);
                }
        }
    }

    // epilogue: /deg, store
#pragma unroll
    for (int mf = 0; mf < 4; ++mf) {
        const int r0 = bm + warp_m + mf * 16 + (lane >> 2);
        const int r1 = r0 + 8;
        float inv0 = 0.f, inv1 = 0.f;
        if (r0 < C) inv0 = 1.f / (float)(__ldg(ptr + r0 + 1) - __ldg(ptr + r0));
        if (r1 < C) inv1 = 1.f / (float)(__ldg(ptr + r1 + 1) - __ldg(ptr + r1));
#pragma unroll
        for (int nf = 0; nf < 4; ++nf) {
            const int col = bn + warp_n + nf * 8 + (lane & 3) * 2;
            if (r0 < C) {
                float2 o; o.x = acc[mf][nf][0] * inv0; o.y = acc[mf][nf][1] * inv0;
                *(float2*)(out + (size_t)r0 * DFEAT + col) = o;
            }
            if (r1 < C) {
                float2 o; o.x = acc[mf][nf][2] * inv1; o.y = acc[mf][nf][3] * inv1;
                *(float2*)(out + (size_t)r1 * DFEAT + col) = o;
            }
        }
    }
}

// ---------------------------------------------------------------------------
extern "C" void kernel_launch(void* const* d_in, const int* in_sizes, int n_in,
                              void* d_out, int out_size) {
    const float* x   = (const float*)d_in[0];
    const float* w   = (const float*)d_in[1];
    const int*   ptr = (const int*)d_in[2];
    const int*   idx = (const int*)d_in[3];
    const int*   rel = (const int*)d_in[4];
    float*       out = (float*)d_out;

    const int C    = in_sizes[2] - 1;
    const int nblk = (C + 127) / 128;
    const int xn2  = in_sizes[0] / 2;

    cudaFuncSetAttribute(gemm_kernel,
                         cudaFuncAttributeMaxDynamicSharedMemorySize, SMEMSZ);

    wsplit_kernel<<<(DFEAT * KDIM) / 256, 256>>>(w);
    xconv_kernel<<<(xn2 + 255) / 256, 256>>>(x, xn2);
    sort_kernel<<<(C + 255) / 256, 256>>>(ptr, idx, rel, C);
    agg_kernel<<<(C + 3) / 4, 128>>>(ptr, C);

    dim3 grid(nblk, DFEAT / 128);
    gemm_kernel<<<grid, 256, SMEMSZ>>>(ptr, out, C);
}